// round 1
// baseline (speedup 1.0000x reference)
#include <cuda_runtime.h>
#include <cstdint>

// Problem constants
#define Bb    2
#define Ll    32768            // T*H*W = 8*64*64
#define Cc    128
#define NTOK  512              // tokens per window (2*64*4)
#define NHEADS 4
#define HDIM  32
// window decomposition: w = b*64 + tB*16 + wB ; n = t*256 + h*4 + ws
// l(global) = (tB*2 + t)*4096 + h*64 + wB*4 + ws

static __device__ __forceinline__ float ex2f(float x){
    float y; asm("ex2.approx.ftz.f32 %0, %1;" : "=f"(y) : "f"(x)); return y;
}
static __device__ __forceinline__ unsigned long long fma2(unsigned long long a, unsigned long long b, unsigned long long c){
    unsigned long long d; asm("fma.rn.f32x2 %0, %1, %2, %3;" : "=l"(d) : "l"(a), "l"(b), "l"(c)); return d;
}
static __device__ __forceinline__ unsigned long long mul2(unsigned long long a, unsigned long long b){
    unsigned long long d; asm("mul.rn.f32x2 %0, %1, %2;" : "=l"(d) : "l"(a), "l"(b)); return d;
}
static __device__ __forceinline__ unsigned long long pack2(float x, float y){
    unsigned long long d; asm("mov.b64 %0, {%1, %2};" : "=l"(d) : "f"(x), "f"(y)); return d;
}
static __device__ __forceinline__ float2 unpack2(unsigned long long a){
    float2 r; asm("mov.b64 {%0, %1}, %2;" : "=f"(r.x), "=f"(r.y) : "l"(a)); return r;
}
static __device__ __forceinline__ uint32_t s2u(const void* p){
    uint32_t a;
    asm("{ .reg .u64 t; cvta.to.shared.u64 t, %1; cvt.u32.u64 %0, t; }" : "=r"(a) : "l"(p));
    return a;
}
static __device__ __forceinline__ void lds2u64(uint32_t a, unsigned long long& x, unsigned long long& y){
    asm volatile("ld.shared.v2.u64 {%0, %1}, [%2];" : "=l"(x), "=l"(y) : "r"(a));
}

// smem layout (floats):
//   Ks : 512*32            (K rows, 128B stride; broadcast reads only)
//   Vs : 512*36            (V rows padded to 144B so epilogue strided LDS.128 is conflict-free)
//   Ws : 27*32             ([tap][d] depthwise weights for this head)
//   Bs : 32                (bias)
#define SMEM_FLOATS (NTOK*32 + NTOK*36 + 27*32 + 32)   // 35712 floats = 142848 B

__global__ void __launch_bounds__(256, 1)
lepe_attn_kernel(const float* __restrict__ qkv,
                 const float* __restrict__ lw,
                 const float* __restrict__ lb,
                 float* __restrict__ out)
{
    extern __shared__ float sm[];
    float* Ks  = sm;
    float* Vs  = sm + NTOK*32;
    float* Wsm = Vs + NTOK*36;
    float* Bsm = Wsm + 27*32;

    const int bx   = blockIdx.x;          // 0..1023
    const int w    = bx >> 3;             // window 0..127
    const int head = (bx >> 1) & 3;
    const int half = bx & 1;
    const int b  = w >> 6;
    const int tB = (w >> 4) & 3;
    const int wB = w & 15;
    const int tid = threadIdx.x;

    const size_t batch_off = (size_t)b * Ll * Cc;
    const int chan  = head * HDIM;
    const int lbase = tB*2*4096 + wB*4;

    const float* kglob = qkv + (size_t)1 * Bb * Ll * Cc + batch_off;
    const float* vglob = qkv + (size_t)2 * Bb * Ll * Cc + batch_off;

    // ---- stage K, V into smem (coalesced: 4 rows x 128B per warp) ----
    {
        const int vec = tid & 7;
        for (int r = (tid >> 3); r < NTOK; r += 32){
            const int t = r >> 8, h = (r >> 2) & 63, ws = r & 3;
            const size_t l = (size_t)(lbase + t*4096 + h*64 + ws);
            float4 kk = ((const float4*)(kglob + l*Cc + chan))[vec];
            float4 vv = ((const float4*)(vglob + l*Cc + chan))[vec];
            ((float4*)(Ks + r*32))[vec] = kk;
            *((float4*)(Vs + r*36 + vec*4)) = vv;
        }
        for (int idx = tid; idx < 27*32; idx += 256){
            const int tap = idx >> 5, d = idx & 31;
            Wsm[tap*32 + d] = lw[(chan + d)*27 + tap];
        }
        if (tid < 32) Bsm[tid] = lb[chan + tid];
    }

    // ---- this thread's query row (pre-scaled into log2 domain) ----
    const int row = half*256 + tid;
    const int rt = row >> 8, rh = (row >> 2) & 63, rws = row & 3;
    const size_t lrow = (size_t)(lbase + rt*4096 + rh*64 + rws);

    unsigned long long q2[16];
    {
        const float sc = 0.17677669529663689f * 1.4426950408889634f; // scale * log2(e)
        const float4* qg = (const float4*)(qkv + batch_off + lrow*Cc + chan);
        #pragma unroll
        for (int v = 0; v < 8; v++){
            float4 qq = qg[v];
            q2[2*v]   = pack2(qq.x*sc, qq.y*sc);
            q2[2*v+1] = pack2(qq.z*sc, qq.w*sc);
        }
    }
    __syncthreads();

    const uint32_t KsA = s2u(Ks);
    const uint32_t VsA = s2u(Vs);

    unsigned long long o2[16];
    #pragma unroll
    for (int t = 0; t < 16; t++) o2[t] = 0ull;   // packed (0,0)
    float m = -1e30f, lsum = 0.f;

    // ---- flash mainloop: chunks of 16 keys; K/V reads are warp-broadcast ----
    for (int j0 = 0; j0 < NTOK; j0 += 16){
        float s[16];
        #pragma unroll
        for (int jj = 0; jj < 16; jj++){
            const uint32_t ka = KsA + (uint32_t)(j0 + jj)*128;
            unsigned long long acc0 = 0ull, acc1 = 0ull, acc2 = 0ull, acc3 = 0ull;
            unsigned long long k0, k1;
            #pragma unroll
            for (int v = 0; v < 8; v += 2){
                lds2u64(ka + v*16, k0, k1);
                acc0 = fma2(q2[2*v],   k0, acc0);
                acc1 = fma2(q2[2*v+1], k1, acc1);
                lds2u64(ka + (v+1)*16, k0, k1);
                acc2 = fma2(q2[2*v+2], k0, acc2);
                acc3 = fma2(q2[2*v+3], k1, acc3);
            }
            acc0 = fma2(pack2(1.f,1.f), acc1, acc0);   // acc0 += acc1 (packed add via fma)
            acc2 = fma2(pack2(1.f,1.f), acc3, acc2);
            float2 a = unpack2(acc0);
            float2 c = unpack2(acc2);
            s[jj] = (a.x + a.y) + (c.x + c.y);
        }
        float cm = s[0];
        #pragma unroll
        for (int jj = 1; jj < 16; jj++) cm = fmaxf(cm, s[jj]);
        const float nm   = fmaxf(m, cm);
        const float corr = ex2f(m - nm);
        m = nm;
        float psum = 0.f;
        #pragma unroll
        for (int jj = 0; jj < 16; jj++){ s[jj] = ex2f(s[jj] - nm); psum += s[jj]; }
        lsum = lsum*corr + psum;
        const unsigned long long c2 = pack2(corr, corr);
        #pragma unroll
        for (int t = 0; t < 16; t++) o2[t] = mul2(o2[t], c2);
        #pragma unroll
        for (int jj = 0; jj < 16; jj++){
            const uint32_t va = VsA + (uint32_t)(j0 + jj)*144;
            const unsigned long long p2 = pack2(s[jj], s[jj]);
            unsigned long long v0, v1;
            #pragma unroll
            for (int v = 0; v < 8; v++){
                lds2u64(va + v*16, v0, v1);
                o2[2*v]   = fma2(p2, v0, o2[2*v]);
                o2[2*v+1] = fma2(p2, v1, o2[2*v+1]);
            }
        }
    }

    // normalize
    {
        const float inv = 1.f / lsum;
        const unsigned long long i2 = pack2(inv, inv);
        #pragma unroll
        for (int t = 0; t < 16; t++) o2[t] = mul2(o2[t], i2);
    }

    // ---- fused LePE: depthwise 3x3x3 over the window (zero pad), from smem V ----
    const uint32_t WsA = s2u(Wsm);
    #pragma unroll
    for (int dt = -1; dt <= 1; dt++){
        const int tt = rt + dt;
        if ((unsigned)tt >= 2u) continue;
        #pragma unroll
        for (int dh = -1; dh <= 1; dh++){
            const int hh = rh + dh;
            if ((unsigned)hh >= 64u) continue;
            #pragma unroll
            for (int dw = -1; dw <= 1; dw++){
                const int ww2 = rws + dw;
                if ((unsigned)ww2 >= 4u) continue;
                const int n2  = tt*256 + hh*4 + ww2;
                const int tap = (dt+1)*9 + (dh+1)*3 + (dw+1);
                const uint32_t va = VsA + (uint32_t)n2*144;
                const uint32_t wa = WsA + (uint32_t)tap*128;
                #pragma unroll
                for (int v = 0; v < 8; v++){
                    unsigned long long v0, v1, w0, w1;
                    lds2u64(va + v*16, v0, v1);
                    lds2u64(wa + v*16, w0, w1);
                    o2[2*v]   = fma2(v0, w0, o2[2*v]);
                    o2[2*v+1] = fma2(v1, w1, o2[2*v+1]);
                }
            }
        }
    }

    // ---- bias + store (contiguous 128B per thread) ----
    float* op = out + batch_off + lrow*Cc + chan;
    #pragma unroll
    for (int v = 0; v < 8; v++){
        float2 a  = unpack2(o2[2*v]);
        float2 bb = unpack2(o2[2*v+1]);
        float4 r4;
        r4.x = a.x  + Bsm[4*v + 0];
        r4.y = a.y  + Bsm[4*v + 1];
        r4.z = bb.x + Bsm[4*v + 2];
        r4.w = bb.y + Bsm[4*v + 3];
        ((float4*)op)[v] = r4;
    }
}

extern "C" void kernel_launch(void* const* d_in, const int* in_sizes, int n_in,
                              void* d_out, int out_size)
{
    const float* qkv = (const float*)d_in[0];
    const float* lw  = (const float*)d_in[1];
    const float* lb  = (const float*)d_in[2];
    float* out       = (float*)d_out;

    const int smem_bytes = SMEM_FLOATS * 4;   // 142848
    cudaFuncSetAttribute(lepe_attn_kernel, cudaFuncAttributeMaxDynamicSharedMemorySize, smem_bytes);
    lepe_attn_kernel<<<1024, 256, smem_bytes>>>(qkv, lw, lb, out);
}

// round 2
// speedup vs baseline: 1.1642x; 1.1642x over previous
#include <cuda_runtime.h>
#include <cstdint>

// Problem constants
#define Bb    2
#define Ll    32768            // T*H*W = 8*64*64
#define Cc    128
#define NTOK  512              // tokens per window (2*64*4)
#define NHEADS 4
#define HDIM  32
// window decomposition: w = b*64 + tB*16 + wB ; n = t*256 + h*4 + ws
// l(global) = (tB*2 + t)*4096 + h*64 + wB*4 + ws

static __device__ __forceinline__ float ex2f(float x){
    float y; asm("ex2.approx.ftz.f32 %0, %1;" : "=f"(y) : "f"(x)); return y;
}
static __device__ __forceinline__ unsigned long long fma2(unsigned long long a, unsigned long long b, unsigned long long c){
    unsigned long long d; asm("fma.rn.f32x2 %0, %1, %2, %3;" : "=l"(d) : "l"(a), "l"(b), "l"(c)); return d;
}
static __device__ __forceinline__ unsigned long long add2(unsigned long long a, unsigned long long b){
    unsigned long long d; asm("add.rn.f32x2 %0, %1, %2;" : "=l"(d) : "l"(a), "l"(b)); return d;
}
static __device__ __forceinline__ unsigned long long mul2(unsigned long long a, unsigned long long b){
    unsigned long long d; asm("mul.rn.f32x2 %0, %1, %2;" : "=l"(d) : "l"(a), "l"(b)); return d;
}
static __device__ __forceinline__ unsigned long long pack2(float x, float y){
    unsigned long long d; asm("mov.b64 %0, {%1, %2};" : "=l"(d) : "f"(x), "f"(y)); return d;
}
static __device__ __forceinline__ float2 unpack2(unsigned long long a){
    float2 r; asm("mov.b64 {%0, %1}, %2;" : "=f"(r.x), "=f"(r.y) : "l"(a)); return r;
}
static __device__ __forceinline__ uint32_t s2u(const void* p){
    uint32_t a;
    asm("{ .reg .u64 t; cvta.to.shared.u64 t, %1; cvt.u32.u64 %0, t; }" : "=r"(a) : "l"(p));
    return a;
}
static __device__ __forceinline__ void lds2u64(uint32_t a, unsigned long long& x, unsigned long long& y){
    asm volatile("ld.shared.v2.u64 {%0, %1}, [%2];" : "=l"(x), "=l"(y) : "r"(a));
}

// smem layout (floats):
//   Ks : 512*32            (K rows, 128B stride; broadcast reads only)
//   Vs : 512*36            (V rows padded to 144B so epilogue strided LDS.128 is conflict-free)
//   Ws : 27*32             ([tap][d] depthwise weights for this head)
//   Bs : 32                (bias)
#define SMEM_FLOATS (NTOK*32 + NTOK*36 + 27*32 + 32)   // 35712 floats = 142848 B

#define CHUNK 8

__global__ void __launch_bounds__(256, 1)
lepe_attn_kernel(const float* __restrict__ qkv,
                 const float* __restrict__ lw,
                 const float* __restrict__ lb,
                 float* __restrict__ out)
{
    extern __shared__ float sm[];
    float* Ks  = sm;
    float* Vs  = sm + NTOK*32;
    float* Wsm = Vs + NTOK*36;
    float* Bsm = Wsm + 27*32;

    const int bx   = blockIdx.x;          // 0..511 : (window, head)
    const int w    = bx >> 2;             // window 0..127
    const int head = bx & 3;
    const int b  = w >> 6;
    const int tB = (w >> 4) & 3;
    const int wB = w & 15;
    const int tid = threadIdx.x;

    const size_t batch_off = (size_t)b * Ll * Cc;
    const int chan  = head * HDIM;
    const int lbase = tB*2*4096 + wB*4;

    const float* kglob = qkv + (size_t)1 * Bb * Ll * Cc + batch_off;
    const float* vglob = qkv + (size_t)2 * Bb * Ll * Cc + batch_off;

    // ---- stage K, V into smem (coalesced: 4 rows x 128B per warp) ----
    {
        const int vec = tid & 7;
        for (int r = (tid >> 3); r < NTOK; r += 32){
            const int t = r >> 8, h = (r >> 2) & 63, ws = r & 3;
            const size_t l = (size_t)(lbase + t*4096 + h*64 + ws);
            float4 kk = ((const float4*)(kglob + l*Cc + chan))[vec];
            float4 vv = ((const float4*)(vglob + l*Cc + chan))[vec];
            ((float4*)(Ks + r*32))[vec] = kk;
            *((float4*)(Vs + r*36 + vec*4)) = vv;
        }
        for (int idx = tid; idx < 27*32; idx += 256){
            const int tap = idx >> 5, d = idx & 31;
            Wsm[tap*32 + d] = lw[(chan + d)*27 + tap];
        }
        if (tid < 32) Bsm[tid] = lb[chan + tid];
    }

    // ---- this thread's TWO query rows (pre-scaled into log2 domain) ----
    const int rowA = tid;          // 0..255
    const int rowB = tid + 256;    // 256..511
    const int rtA = rowA >> 8, rhA = (rowA >> 2) & 63, rwsA = rowA & 3;
    const int rtB = rowB >> 8, rhB = (rowB >> 2) & 63, rwsB = rowB & 3;
    const size_t lrowA = (size_t)(lbase + rtA*4096 + rhA*64 + rwsA);
    const size_t lrowB = (size_t)(lbase + rtB*4096 + rhB*64 + rwsB);

    unsigned long long qa[16], qb[16];
    {
        const float sc = 0.17677669529663689f * 1.4426950408889634f; // scale * log2(e)
        const float4* qgA = (const float4*)(qkv + batch_off + lrowA*Cc + chan);
        const float4* qgB = (const float4*)(qkv + batch_off + lrowB*Cc + chan);
        #pragma unroll
        for (int v = 0; v < 8; v++){
            float4 q1 = qgA[v];
            qa[2*v]   = pack2(q1.x*sc, q1.y*sc);
            qa[2*v+1] = pack2(q1.z*sc, q1.w*sc);
            float4 q2v = qgB[v];
            qb[2*v]   = pack2(q2v.x*sc, q2v.y*sc);
            qb[2*v+1] = pack2(q2v.z*sc, q2v.w*sc);
        }
    }
    __syncthreads();

    const uint32_t KsA = s2u(Ks);
    const uint32_t VsA = s2u(Vs);

    unsigned long long oa[16], ob[16];
    #pragma unroll
    for (int t = 0; t < 16; t++){ oa[t] = 0ull; ob[t] = 0ull; }
    float mA = -1e30f, lsA = 0.f;
    float mB = -1e30f, lsB = 0.f;

    // ---- flash mainloop: chunks of CHUNK keys; K/V loaded once, used for both rows ----
    for (int j0 = 0; j0 < NTOK; j0 += CHUNK){
        float sa[CHUNK], sb[CHUNK];
        #pragma unroll
        for (int jj = 0; jj < CHUNK; jj++){
            const uint32_t ka = KsA + (uint32_t)(j0 + jj)*128;
            unsigned long long a0=0ull,a1=0ull,a2=0ull,a3=0ull;
            unsigned long long b0=0ull,b1=0ull,b2=0ull,b3=0ull;
            unsigned long long k0, k1, k2, k3;
            #pragma unroll
            for (int v = 0; v < 8; v += 2){
                lds2u64(ka + v*16, k0, k1);
                a0 = fma2(qa[2*v],   k0, a0);
                a1 = fma2(qa[2*v+1], k1, a1);
                b0 = fma2(qb[2*v],   k0, b0);
                b1 = fma2(qb[2*v+1], k1, b1);
                lds2u64(ka + (v+1)*16, k2, k3);
                a2 = fma2(qa[2*v+2], k2, a2);
                a3 = fma2(qa[2*v+3], k3, a3);
                b2 = fma2(qb[2*v+2], k2, b2);
                b3 = fma2(qb[2*v+3], k3, b3);
            }
            a0 = add2(a0, a1); a2 = add2(a2, a3); a0 = add2(a0, a2);
            b0 = add2(b0, b1); b2 = add2(b2, b3); b0 = add2(b0, b2);
            float2 fa = unpack2(a0);
            float2 fb = unpack2(b0);
            sa[jj] = fa.x + fa.y;
            sb[jj] = fb.x + fb.y;
        }
        // online softmax update (row A)
        float cmA = sa[0], cmB = sb[0];
        #pragma unroll
        for (int jj = 1; jj < CHUNK; jj++){ cmA = fmaxf(cmA, sa[jj]); cmB = fmaxf(cmB, sb[jj]); }
        const float nmA = fmaxf(mA, cmA);
        const float nmB = fmaxf(mB, cmB);
        const float corrA = ex2f(mA - nmA);
        const float corrB = ex2f(mB - nmB);
        mA = nmA; mB = nmB;
        float psA = 0.f, psB = 0.f;
        #pragma unroll
        for (int jj = 0; jj < CHUNK; jj++){
            sa[jj] = ex2f(sa[jj] - nmA); psA += sa[jj];
            sb[jj] = ex2f(sb[jj] - nmB); psB += sb[jj];
        }
        lsA = lsA*corrA + psA;
        lsB = lsB*corrB + psB;
        const unsigned long long cA2 = pack2(corrA, corrA);
        const unsigned long long cB2 = pack2(corrB, corrB);
        #pragma unroll
        for (int t = 0; t < 16; t++){ oa[t] = mul2(oa[t], cA2); ob[t] = mul2(ob[t], cB2); }
        // PV accumulate: V row loaded once, used for both query rows
        #pragma unroll
        for (int jj = 0; jj < CHUNK; jj++){
            const uint32_t va = VsA + (uint32_t)(j0 + jj)*144;
            const unsigned long long pa2 = pack2(sa[jj], sa[jj]);
            const unsigned long long pb2 = pack2(sb[jj], sb[jj]);
            unsigned long long v0, v1;
            #pragma unroll
            for (int v = 0; v < 8; v++){
                lds2u64(va + v*16, v0, v1);
                oa[2*v]   = fma2(pa2, v0, oa[2*v]);
                oa[2*v+1] = fma2(pa2, v1, oa[2*v+1]);
                ob[2*v]   = fma2(pb2, v0, ob[2*v]);
                ob[2*v+1] = fma2(pb2, v1, ob[2*v+1]);
            }
        }
    }

    // normalize
    {
        const float invA = 1.f / lsA;
        const float invB = 1.f / lsB;
        const unsigned long long iA2 = pack2(invA, invA);
        const unsigned long long iB2 = pack2(invB, invB);
        #pragma unroll
        for (int t = 0; t < 16; t++){ oa[t] = mul2(oa[t], iA2); ob[t] = mul2(ob[t], iB2); }
    }

    // ---- fused LePE + bias + store, per query row ----
    const uint32_t WsA = s2u(Wsm);
    #pragma unroll
    for (int r = 0; r < 2; r++){
        unsigned long long* o2 = r ? ob : oa;
        const int rt  = r ? rtB  : rtA;
        const int rh  = r ? rhB  : rhA;
        const int rws = r ? rwsB : rwsA;
        const size_t lrow = r ? lrowB : lrowA;

        #pragma unroll
        for (int dt = -1; dt <= 1; dt++){
            const int tt = rt + dt;
            if ((unsigned)tt >= 2u) continue;
            #pragma unroll
            for (int dh = -1; dh <= 1; dh++){
                const int hh = rh + dh;
                if ((unsigned)hh >= 64u) continue;
                #pragma unroll
                for (int dw = -1; dw <= 1; dw++){
                    const int ww2 = rws + dw;
                    if ((unsigned)ww2 >= 4u) continue;
                    const int n2  = tt*256 + hh*4 + ww2;
                    const int tap = (dt+1)*9 + (dh+1)*3 + (dw+1);
                    const uint32_t va = VsA + (uint32_t)n2*144;
                    const uint32_t wa = WsA + (uint32_t)tap*128;
                    #pragma unroll
                    for (int v = 0; v < 8; v++){
                        unsigned long long v0, v1, w0, w1;
                        lds2u64(va + v*16, v0, v1);
                        lds2u64(wa + v*16, w0, w1);
                        o2[2*v]   = fma2(v0, w0, o2[2*v]);
                        o2[2*v+1] = fma2(v1, w1, o2[2*v+1]);
                    }
                }
            }
        }

        float* op = out + batch_off + lrow*Cc + chan;
        #pragma unroll
        for (int v = 0; v < 8; v++){
            float2 x  = unpack2(o2[2*v]);
            float2 y  = unpack2(o2[2*v+1]);
            float4 r4;
            r4.x = x.x + Bsm[4*v + 0];
            r4.y = x.y + Bsm[4*v + 1];
            r4.z = y.x + Bsm[4*v + 2];
            r4.w = y.y + Bsm[4*v + 3];
            ((float4*)op)[v] = r4;
        }
    }
}

extern "C" void kernel_launch(void* const* d_in, const int* in_sizes, int n_in,
                              void* d_out, int out_size)
{
    const float* qkv = (const float*)d_in[0];
    const float* lw  = (const float*)d_in[1];
    const float* lb  = (const float*)d_in[2];
    float* out       = (float*)d_out;

    const int smem_bytes = SMEM_FLOATS * 4;   // 142848
    cudaFuncSetAttribute(lepe_attn_kernel, cudaFuncAttributeMaxDynamicSharedMemorySize, smem_bytes);
    lepe_attn_kernel<<<512, 256, smem_bytes>>>(qkv, lw, lb, out);
}